// round 5
// baseline (speedup 1.0000x reference)
#include <cuda_runtime.h>
#include <cuda_bf16.h>

#define NUM_BINS    15
#define NUM_CLASSES 19
#define HW          (512 * 512)
#define BATCH       8

// Grid: x = spatial float4-groups per image (HW/4 / 256 = 256 blocks),
//       y = batch (8). Each thread handles 4 consecutive pixels of one image,
// holding all 19 class values in registers (one float4 per class).
// Layout [B, C, H, W]: class stride = HW floats = HW/4 float4s.
__global__ __launch_bounds__(256, 1)
void calib_kernel(const float* __restrict__ logits,
                  const float* __restrict__ val_freqs,
                  float* __restrict__ out)
{
    __shared__ float sfreq[NUM_CLASSES * NUM_BINS];  // 285 floats
    for (int i = threadIdx.x; i < NUM_CLASSES * NUM_BINS; i += blockDim.x)
        sfreq[i] = val_freqs[i];                      // covers all 285 entries
    __syncthreads();

    const int s4 = blockIdx.x * blockDim.x + threadIdx.x;   // float4 index in image
    const int b  = blockIdx.y;

    const long long base_off = (long long)b * (NUM_CLASSES * HW);
    const float4* __restrict__ in4  = (const float4*)(logits + base_off) + s4;
    float4*       __restrict__ out4 = (float4*)(out + base_off) + s4;
    const int cstride4 = HW / 4;             // class stride in float4 units

    // ---- load all 19 classes (front-batched, high MLP) ----
    float4 v[NUM_CLASSES];
    #pragma unroll
    for (int c = 0; c < NUM_CLASSES; c++)
        v[c] = in4[c * cstride4];

    // ---- per-lane max over classes ----
    float4 mx = v[0];
    #pragma unroll
    for (int c = 1; c < NUM_CLASSES; c++) {
        mx.x = fmaxf(mx.x, v[c].x);
        mx.y = fmaxf(mx.y, v[c].y);
        mx.z = fmaxf(mx.z, v[c].z);
        mx.w = fmaxf(mx.w, v[c].w);
    }

    // ---- exp(x - max), sum ----
    float4 sum = make_float4(0.f, 0.f, 0.f, 0.f);
    #pragma unroll
    for (int c = 0; c < NUM_CLASSES; c++) {
        v[c].x = expf(v[c].x - mx.x);  sum.x += v[c].x;
        v[c].y = expf(v[c].y - mx.y);  sum.y += v[c].y;
        v[c].z = expf(v[c].z - mx.z);  sum.z += v[c].z;
        v[c].w = expf(v[c].w - mx.w);  sum.w += v[c].w;
    }
    float4 inv;
    inv.x = 1.0f / sum.x;
    inv.y = 1.0f / sum.y;
    inv.z = 1.0f / sum.z;
    inv.w = 1.0f / sum.w;

    // ---- bin + gather + class-sum (cal overwrites v in place) ----
    float4 csum = make_float4(0.f, 0.f, 0.f, 0.f);
    #pragma unroll
    for (int c = 0; c < NUM_CLASSES; c++) {
        const float* f = sfreq + c * NUM_BINS;
        int bx = min((int)(v[c].x * inv.x * (float)NUM_BINS), NUM_BINS - 1);
        int by = min((int)(v[c].y * inv.y * (float)NUM_BINS), NUM_BINS - 1);
        int bz = min((int)(v[c].z * inv.z * (float)NUM_BINS), NUM_BINS - 1);
        int bw = min((int)(v[c].w * inv.w * (float)NUM_BINS), NUM_BINS - 1);
        v[c].x = f[bx];  csum.x += v[c].x;
        v[c].y = f[by];  csum.y += v[c].y;
        v[c].z = f[bz];  csum.z += v[c].z;
        v[c].w = f[bw];  csum.w += v[c].w;
    }

    // ---- normalize (guard s==0 -> 1, matching reference) ----
    csum.x = (csum.x == 0.f) ? 1.f : csum.x;
    csum.y = (csum.y == 0.f) ? 1.f : csum.y;
    csum.z = (csum.z == 0.f) ? 1.f : csum.z;
    csum.w = (csum.w == 0.f) ? 1.f : csum.w;
    float4 invc;
    invc.x = 1.0f / csum.x;
    invc.y = 1.0f / csum.y;
    invc.z = 1.0f / csum.z;
    invc.w = 1.0f / csum.w;

    // ---- store ----
    #pragma unroll
    for (int c = 0; c < NUM_CLASSES; c++) {
        float4 o;
        o.x = v[c].x * invc.x;
        o.y = v[c].y * invc.y;
        o.z = v[c].z * invc.z;
        o.w = v[c].w * invc.w;
        out4[c * cstride4] = o;
    }
}

extern "C" void kernel_launch(void* const* d_in, const int* in_sizes, int n_in,
                              void* d_out, int out_size)
{
    const float* logits    = (const float*)d_in[0];  // [8,19,512,512] f32
    const float* val_freqs = (const float*)d_in[1];  // [19,15] f32
    float* out = (float*)d_out;

    dim3 grid((HW / 4) / 256, BATCH);   // (256, 8)
    calib_kernel<<<grid, 256>>>(logits, val_freqs, out);
}

// round 7
// speedup vs baseline: 1.3779x; 1.3779x over previous
#include <cuda_runtime.h>
#include <cuda_bf16.h>

#define NUM_BINS    15
#define NUM_CLASSES 19
#define HW          (512 * 512)
#define BATCH       8

// One pixel per thread. Grid: x = HW/256 blocks, y = batch.
// 19 class values live in registers (~19 floats payload), launch_bounds caps
// regs at 85 -> 3 blocks/SM -> 24 warps/SM (vs 8 in the float4 version).
// Warp loads 32 consecutive floats per class -> one 128B line, fully coalesced.
__global__ __launch_bounds__(256, 3)
void calib_kernel(const float* __restrict__ logits,
                  const float* __restrict__ val_freqs,
                  float* __restrict__ out)
{
    __shared__ float sfreq[NUM_CLASSES * NUM_BINS];  // 285 floats
    for (int i = threadIdx.x; i < NUM_CLASSES * NUM_BINS; i += blockDim.x)
        sfreq[i] = val_freqs[i];
    __syncthreads();

    const int s = blockIdx.x * blockDim.x + threadIdx.x;  // pixel in image
    const int b = blockIdx.y;

    const float* __restrict__ in  = logits + (long long)b * (NUM_CLASSES * HW) + s;
    float*       __restrict__ outp = out   + (long long)b * (NUM_CLASSES * HW) + s;

    // ---- load all 19 classes (front-batched, high MLP) ----
    float v[NUM_CLASSES];
    #pragma unroll
    for (int c = 0; c < NUM_CLASSES; c++)
        v[c] = in[c * HW];

    // ---- max over classes ----
    float mx = v[0];
    #pragma unroll
    for (int c = 1; c < NUM_CLASSES; c++)
        mx = fmaxf(mx, v[c]);

    // ---- exp(x - max), sum ----
    float sum = 0.f;
    #pragma unroll
    for (int c = 0; c < NUM_CLASSES; c++) {
        v[c] = expf(v[c] - mx);
        sum += v[c];
    }
    const float scale = (float)NUM_BINS / sum;   // bin = floor(e_c * 15 / sum)

    // ---- bin + table gather + class-sum (cal overwrites v in place) ----
    float csum = 0.f;
    #pragma unroll
    for (int c = 0; c < NUM_CLASSES; c++) {
        int bin = min((int)(v[c] * scale), NUM_BINS - 1);
        v[c] = sfreq[c * NUM_BINS + bin];
        csum += v[c];
    }

    // ---- normalize (guard s==0 -> 1, matching reference) ----
    csum = (csum == 0.f) ? 1.f : csum;
    const float invc = 1.0f / csum;

    // ---- store ----
    #pragma unroll
    for (int c = 0; c < NUM_CLASSES; c++)
        outp[c * HW] = v[c] * invc;
}

extern "C" void kernel_launch(void* const* d_in, const int* in_sizes, int n_in,
                              void* d_out, int out_size)
{
    const float* logits    = (const float*)d_in[0];  // [8,19,512,512] f32
    const float* val_freqs = (const float*)d_in[1];  // [19,15] f32
    float* out = (float*)d_out;

    dim3 grid(HW / 256, BATCH);   // (1024, 8)
    calib_kernel<<<grid, 256>>>(logits, val_freqs, out);
}

// round 8
// speedup vs baseline: 1.4511x; 1.0531x over previous
#include <cuda_runtime.h>
#include <cuda_bf16.h>

#define NUM_BINS    15
#define NUM_CLASSES 19
#define HW          (512 * 512)
#define BATCH       8

// One pixel per thread. Grid: x = HW/256 blocks, y = batch.
// launch_bounds(256,6) caps regs at 42 -> 6 blocks = 48 warps/SM (75% occ).
// __ldcs/__stcs: data is read-once/write-once, evict-first keeps L2 clean.
// Warp loads 32 consecutive floats per class -> one 128B line, fully coalesced.
__global__ __launch_bounds__(256, 6)
void calib_kernel(const float* __restrict__ logits,
                  const float* __restrict__ val_freqs,
                  float* __restrict__ out)
{
    __shared__ float sfreq[NUM_CLASSES * NUM_BINS];  // 285 floats
    for (int i = threadIdx.x; i < NUM_CLASSES * NUM_BINS; i += blockDim.x)
        sfreq[i] = val_freqs[i];
    __syncthreads();

    const int s = blockIdx.x * blockDim.x + threadIdx.x;  // pixel in image
    const int b = blockIdx.y;

    const float* __restrict__ in   = logits + (long long)b * (NUM_CLASSES * HW) + s;
    float*       __restrict__ outp = out    + (long long)b * (NUM_CLASSES * HW) + s;

    // ---- load all 19 classes (front-batched, high MLP, streaming) ----
    float v[NUM_CLASSES];
    #pragma unroll
    for (int c = 0; c < NUM_CLASSES; c++)
        v[c] = __ldcs(in + c * HW);

    // ---- max over classes ----
    float mx = v[0];
    #pragma unroll
    for (int c = 1; c < NUM_CLASSES; c++)
        mx = fmaxf(mx, v[c]);

    // ---- exp(x - max), sum ----
    float sum = 0.f;
    #pragma unroll
    for (int c = 0; c < NUM_CLASSES; c++) {
        v[c] = expf(v[c] - mx);
        sum += v[c];
    }
    const float scale = (float)NUM_BINS / sum;   // bin = floor(e_c * 15 / sum)

    // ---- bin + table gather + class-sum (cal overwrites v in place) ----
    float csum = 0.f;
    #pragma unroll
    for (int c = 0; c < NUM_CLASSES; c++) {
        int bin = min((int)(v[c] * scale), NUM_BINS - 1);
        v[c] = sfreq[c * NUM_BINS + bin];
        csum += v[c];
    }

    // ---- normalize (guard s==0 -> 1, matching reference) ----
    csum = (csum == 0.f) ? 1.f : csum;
    const float invc = 1.0f / csum;

    // ---- store (streaming) ----
    #pragma unroll
    for (int c = 0; c < NUM_CLASSES; c++)
        __stcs(outp + c * HW, v[c] * invc);
}

extern "C" void kernel_launch(void* const* d_in, const int* in_sizes, int n_in,
                              void* d_out, int out_size)
{
    const float* logits    = (const float*)d_in[0];  // [8,19,512,512] f32
    const float* val_freqs = (const float*)d_in[1];  // [19,15] f32
    float* out = (float*)d_out;

    dim3 grid(HW / 256, BATCH);   // (1024, 8)
    calib_kernel<<<grid, 256>>>(logits, val_freqs, out);
}